// round 11
// baseline (speedup 1.0000x reference)
#include <cuda_runtime.h>

#define TPB  256
#define MAXB 1024
#define NPAD 8192
#define CCH  30      // k-chunks per row

typedef unsigned long long u64;

__device__ float        g_part[MAXB];
__device__ unsigned int g_ctr;
// SoA staging, NEGATED, mirrored past n (g_n*[m] = -val[m % n]) for wrap-free j
__device__ __align__(16) float g_nzx[NPAD];
__device__ __align__(16) float g_nzy[NPAD];
__device__ __align__(16) float g_nvx[NPAD];
__device__ __align__(16) float g_nvy[NPAD];

__device__ __forceinline__ float ex2_approx(float x) {
    float r; asm("ex2.approx.f32 %0, %1;" : "=f"(r) : "f"(x)); return r;
}
__device__ __forceinline__ float tanh_approx(float x) {
    float r; asm("tanh.approx.f32 %0, %1;" : "=f"(r) : "f"(x)); return r;
}
#define L2E 1.4426950408889634f
#define EK1 1.1283792f
#define EK3 0.100906f
#define SQRTPI_2 0.88622692545275801f

// ---------- packed f32x2 helpers ----------
__device__ __forceinline__ u64 f2pk(float lo, float hi) {
    u64 r; asm("mov.b64 %0, {%1, %2};" : "=l"(r) : "f"(lo), "f"(hi)); return r;
}
__device__ __forceinline__ void f2up(u64 v, float& lo, float& hi) {
    asm("mov.b64 {%0, %1}, %2;" : "=f"(lo), "=f"(hi) : "l"(v));
}
__device__ __forceinline__ u64 f2add(u64 a, u64 b) {
    u64 d; asm("add.rn.f32x2 %0, %1, %2;" : "=l"(d) : "l"(a), "l"(b)); return d;
}
__device__ __forceinline__ u64 f2mul(u64 a, u64 b) {
    u64 d; asm("mul.rn.f32x2 %0, %1, %2;" : "=l"(d) : "l"(a), "l"(b)); return d;
}
__device__ __forceinline__ u64 f2fma(u64 a, u64 b, u64 c) {
    u64 d; asm("fma.rn.f32x2 %0, %1, %2, %3;" : "=l"(d) : "l"(a), "l"(b), "l"(c)); return d;
}
__device__ __forceinline__ u64 f2rsqrt(u64 v) {
    float lo, hi; f2up(v, lo, hi); return f2pk(rsqrtf(lo), rsqrtf(hi));
}
__device__ __forceinline__ u64 f2tanh(u64 v) {
    float lo, hi; f2up(v, lo, hi); return f2pk(tanh_approx(lo), tanh_approx(hi));
}
__device__ __forceinline__ u64 ldg64(const float* p) {
    return __ldg(reinterpret_cast<const u64*>(p));
}

// ---------- scalar erf pieces ----------
__device__ __forceinline__ float erf_tanh(float x) {
    return tanh_approx(x * fmaf(EK3, x * x, EK1));
}
__device__ __forceinline__ float erf_small(float x, float u) {
    float p = fmaf(u, fmaf(u, fmaf(u, -2.3809524e-2f, 0.1f), -0.33333334f), 1.0f);
    return 1.1283791671f * x * p;
}

__device__ __forceinline__ float block_reduce_sum(float v) {
    __shared__ float s[32];
    int lane = threadIdx.x & 31;
    int w    = threadIdx.x >> 5;
    #pragma unroll
    for (int o = 16; o; o >>= 1) v += __shfl_xor_sync(0xffffffffu, v, o);
    if (lane == 0) s[w] = v;
    __syncthreads();
    v = (threadIdx.x < (TPB >> 5)) ? s[threadIdx.x] : 0.0f;
    if (w == 0) {
        #pragma unroll
        for (int o = 16; o; o >>= 1) v += __shfl_xor_sync(0xffffffffu, v, o);
    }
    return v;  // valid in thread 0
}

// scalar pair term
template <bool T0ZERO>
__device__ __forceinline__ float pair_term(float2 zi, float2 vi,
                                           float2 zj, float2 vj,
                                           float b, float t0, float tn) {
    float dzx = zi.x - zj.x, dzy = zi.y - zj.y;
    float dvx = vi.x - vj.x, dvy = vi.y - vj.y;
    float a2 = fmaf(dzx, dzx, dzy * dzy);
    float b2 = fmaf(dvx, dvx, dvy * dvy);
    float ab = fmaf(dzx, dvx, dzy * dvy);
    float rb = rsqrtf(b2);
    float bn = b2 * rb;
    float q  = ab * rb;
    float u  = q * q;
    float earg  = (b - a2) + u;
    float pref  = ex2_approx(earg * L2E) * (SQRTPI_2 * rb);
    float e1 = erf_tanh(fmaf(bn, tn, q));
    float e0 = T0ZERO ? erf_small(q, u) : erf_tanh(fmaf(bn, t0, q));
    return pref * (e1 - e0);
}

// ---------- prep: negated SoA with wrap mirror + counter reset ----------
__global__ void prep(const float2* __restrict__ z0,
                     const float2* __restrict__ v0, int n) {
    int m = blockIdx.x * blockDim.x + threadIdx.x;
    if (m == 0) g_ctr = 0;
    if (m < NPAD) {
        int src = (n > 0) ? (m % n) : 0;
        float2 z = z0[src], v = v0[src];
        g_nzx[m] = -z.x; g_nzy[m] = -z.y;
        g_nvx[m] = -v.x; g_nvy[m] = -v.y;
    }
}

__global__ void __launch_bounds__(TPB, 4)
cvm_fused(const int2*   __restrict__ idx,
          const float*  __restrict__ t,
          const float2* __restrict__ z0,
          const float2* __restrict__ v0,
          const float*  __restrict__ t0p,
          const float*  __restrict__ tnp,
          const float*  __restrict__ betap,
          float*        __restrict__ out,
          int n, int n_events) {
    const float b  = __ldg(betap);
    const float t0 = __ldg(t0p);
    const float tn = __ldg(tnp);
    const float eb886 = SQRTPI_2 * ex2_approx(b * L2E);
    float acc = 0.0f;

    // ---- pair term: circular pairing, per-thread contiguous k-chunk ----
    const int tgl = (int)blockIdx.x * TPB + (int)threadIdx.x;
    const int i   = tgl % n;
    const int c   = tgl / n;
    const int kfull = (n - 1) >> 1;                 // regular k range 1..kfull
    const bool haveHalf = ((n & 1) == 0);

    if (c < CCH && n >= 3) {
        const int cbase = kfull / CCH, crem = kfull % CCH;
        const int kbeg  = 1 + c * cbase + (c < crem ? c : crem);
        const int klen  = cbase + (c < crem ? 1 : 0);

        const float2 zi = __ldg(&z0[i]);
        const float2 vi = __ldg(&v0[i]);

        const bool t0z = (t0 == 0.0f) && (n + kfull + 2 <= NPAD);

        if (t0z) {
            int j0 = i + kbeg;            // unwrapped; mirrored arrays handle >= n
            int j1 = j0 + klen;           // exclusive

            // alignment peel (LDG.64 needs even index)
            if (j0 & 1) {
                int jm = (j0 >= n) ? j0 - n : j0;
                acc += pair_term<true>(zi, vi, __ldg(&z0[jm]), __ldg(&v0[jm]),
                                       b, 0.0f, tn);
                j0++;
            }
            int jp_end = j0 + ((j1 - j0) & ~1);

            // packed constants (broadcast own i values)
            const u64 zxi = f2pk(zi.x, zi.x), zyi = f2pk(zi.y, zi.y);
            const u64 vxi = f2pk(vi.x, vi.x), vyi = f2pk(vi.y, vi.y);
            const u64 NEG1 = f2pk(-1.0f, -1.0f);
            const u64 ONE2 = f2pk(1.0f, 1.0f);
            const u64 TN2  = f2pk(tn, tn);
            const u64 K1   = f2pk(EK1, EK1);
            const u64 K3   = f2pk(EK3, EK3);
            const u64 T0n  = f2pk(-1.1283791671f, -1.1283791671f);
            const u64 T1n  = f2pk(0.3761263890f, 0.3761263890f);
            const u64 T2n  = f2pk(-0.1128379167f, -0.1128379167f);
            const u64 T3n  = f2pk(0.0268661706f, 0.0268661706f);
            const u64 C120 = f2pk(8.3333333e-3f, 8.3333333e-3f);
            const u64 C24  = f2pk(4.1666667e-2f, 4.1666667e-2f);
            const u64 C6_  = f2pk(0.16666667f, 0.16666667f);
            const u64 C2_  = f2pk(0.5f, 0.5f);
            const u64 EB   = f2pk(eb886, eb886);

            u64 acc2 = 0;
            #pragma unroll 2
            for (int J = j0; J < jp_end; J += 2) {
                u64 nzjx = ldg64(g_nzx + J);
                u64 nzjy = ldg64(g_nzy + J);
                u64 nvjx = ldg64(g_nvx + J);
                u64 nvjy = ldg64(g_nvy + J);

                u64 dzx = f2add(zxi, nzjx);
                u64 dzy = f2add(zyi, nzjy);
                u64 dvx = f2add(vxi, nvjx);
                u64 dvy = f2add(vyi, nvjy);

                u64 a2 = f2fma(dzx, dzx, f2mul(dzy, dzy));
                u64 b2 = f2fma(dvx, dvx, f2mul(dvy, dvy));
                u64 ab = f2fma(dzx, dvx, f2mul(dzy, dvy));

                u64 rb = f2rsqrt(b2);
                u64 bn = f2mul(b2, rb);
                u64 q  = f2mul(ab, rb);
                u64 u  = f2mul(q, q);
                u64 w  = f2fma(a2, NEG1, u);       // q^2 - a2 in [-0.5, 0]

                u64 p  = f2fma(w, C120, C24);      // exp(w) Taylor deg-5
                p      = f2fma(w, p, C6_);
                p      = f2fma(w, p, C2_);
                p      = f2fma(w, p, ONE2);
                u64 P  = f2fma(w, p, ONE2);
                u64 pref = f2mul(f2mul(rb, EB), P);

                u64 e0n = f2mul(q, f2fma(u, f2fma(u, f2fma(u, T3n, T2n), T1n), T0n));

                u64 x1 = f2fma(bn, TN2, q);
                u64 h  = f2mul(x1, f2fma(K3, f2mul(x1, x1), K1));
                u64 e1 = f2tanh(h);

                acc2 = f2fma(pref, f2add(e1, e0n), acc2);
            }
            float lo, hi; f2up(acc2, lo, hi);
            acc += lo + hi;

            // odd-tail peel
            if (j1 > jp_end) {
                int jm = (jp_end >= n) ? jp_end - n : jp_end;
                acc += pair_term<true>(zi, vi, __ldg(&z0[jm]), __ldg(&v0[jm]),
                                       b, 0.0f, tn);
            }
            // half-diagonal k = n/2 (even n): owned by last chunk, i < n/2
            if (haveHalf && c == CCH - 1 && i < (n >> 1)) {
                int jm = i + (n >> 1);
                acc += pair_term<true>(zi, vi, __ldg(&z0[jm]), __ldg(&v0[jm]),
                                       b, 0.0f, tn);
            }
        } else {
            // general path (t0 != 0 or n too large for mirror): scalar loop
            for (int k = kbeg; k < kbeg + klen; k++) {
                int jm = i + k; if (jm >= n) jm -= n;
                acc += pair_term<false>(zi, vi, __ldg(&z0[jm]), __ldg(&v0[jm]),
                                        b, t0, tn);
            }
            if (haveHalf && c == CCH - 1 && i < (n >> 1)) {
                int jm = i + (n >> 1);
                acc += pair_term<false>(zi, vi, __ldg(&z0[jm]), __ldg(&v0[jm]),
                                        b, t0, tn);
            }
        }
    }

    // ---- event term (all blocks, uniform grid-stride) ----
    {
        int stride = (int)gridDim.x * TPB;
        for (int e = tgl; e < n_events; e += stride) {
            int2  ij = __ldg(&idx[e]);
            float te = __ldg(&t[e]);
            float2 zi = __ldg(&z0[ij.x]);
            float2 zj = __ldg(&z0[ij.y]);
            float2 vi = __ldg(&v0[ij.x]);
            float2 vj = __ldg(&v0[ij.y]);
            float dx = fmaf(vi.x - vj.x, te, zi.x - zj.x);
            float dy = fmaf(vi.y - vj.y, te, zi.y - zj.y);
            acc = fmaf(dx, dx, acc);
            acc = fmaf(dy, dy, acc);
        }
    }

    float bs = block_reduce_sum(acc);
    __shared__ unsigned int s_rank;
    if (threadIdx.x == 0) {
        g_part[blockIdx.x] = bs;
        __threadfence();
        s_rank = atomicAdd(&g_ctr, 1u);
    }
    __syncthreads();

    if (s_rank == gridDim.x - 1) {
        __threadfence();
        double d = 0.0;
        for (int k = threadIdx.x; k < (int)gridDim.x; k += TPB)
            d += (double)g_part[k];
        __shared__ double sd[32];
        int lane = threadIdx.x & 31, w = threadIdx.x >> 5;
        #pragma unroll
        for (int o = 16; o; o >>= 1) d += __shfl_xor_sync(0xffffffffu, d, o);
        if (lane == 0) sd[w] = d;
        __syncthreads();
        d = (threadIdx.x < (TPB >> 5)) ? sd[threadIdx.x] : 0.0;
        if (w == 0) {
            #pragma unroll
            for (int o = 16; o; o >>= 1) d += __shfl_xor_sync(0xffffffffu, d, o);
        }
        if (threadIdx.x == 0)
            out[0] = (float)((double)n_events * (double)b - d);
    }
}

extern "C" void kernel_launch(void* const* d_in, const int* in_sizes, int n_in,
                              void* d_out, int out_size) {
    const int2*   idx  = (const int2*)d_in[0];    // (N_EVENTS, 2) int32
    const float*  t    = (const float*)d_in[1];   // (N_EVENTS,)
    const float*  t0   = (const float*)d_in[2];   // scalar
    const float*  tn   = (const float*)d_in[3];   // scalar
    const float2* z0   = (const float2*)d_in[4];  // (N_POINTS, 2)
    const float2* v0   = (const float2*)d_in[5];  // (N_POINTS, 2)
    const float*  beta = (const float*)d_in[6];   // (1,1)

    const int n_events = in_sizes[1];
    const int n_points = in_sizes[4] / 2;

    prep<<<(NPAD + 255) / 256, 256>>>(z0, v0, n_points);

    // 4 blocks/SM x 148 SMs = 592 blocks = 151552 lanes >= 30*n lanes needed.
    int grid = 4 * 148;
    cvm_fused<<<grid, TPB>>>(idx, t, z0, v0, t0, tn, beta,
                             (float*)d_out, n_points, n_events);
}

// round 12
// speedup vs baseline: 1.0072x; 1.0072x over previous
#include <cuda_runtime.h>

#define TPB  256
#define MAXB 1024
#define NPAD 8192
#define PWPB 7     // pair warps per block (1 warp does events)

typedef unsigned long long u64;

__device__ float        g_part[MAXB];
__device__ unsigned int g_ctr;
// negated SoA, mirrored past n (pairs); raw packed float4 (event gathers)
__device__ __align__(16) float  g_nzx[NPAD];
__device__ __align__(16) float  g_nzy[NPAD];
__device__ __align__(16) float  g_nvx[NPAD];
__device__ __align__(16) float  g_nvy[NPAD];
__device__ __align__(16) float4 g_zv [NPAD];

__device__ __forceinline__ float ex2_approx(float x) {
    float r; asm("ex2.approx.f32 %0, %1;" : "=f"(r) : "f"(x)); return r;
}
__device__ __forceinline__ float tanh_approx(float x) {
    float r; asm("tanh.approx.f32 %0, %1;" : "=f"(r) : "f"(x)); return r;
}
#define L2E 1.4426950408889634f
#define EK1 1.1283792f
#define EK3 0.100906f
#define SQRTPI_2 0.88622692545275801f

// ---------- packed f32x2 helpers ----------
__device__ __forceinline__ u64 f2pk(float lo, float hi) {
    u64 r; asm("mov.b64 %0, {%1, %2};" : "=l"(r) : "f"(lo), "f"(hi)); return r;
}
__device__ __forceinline__ void f2up(u64 v, float& lo, float& hi) {
    asm("mov.b64 {%0, %1}, %2;" : "=f"(lo), "=f"(hi) : "l"(v));
}
__device__ __forceinline__ u64 f2add(u64 a, u64 b) {
    u64 d; asm("add.rn.f32x2 %0, %1, %2;" : "=l"(d) : "l"(a), "l"(b)); return d;
}
__device__ __forceinline__ u64 f2mul(u64 a, u64 b) {
    u64 d; asm("mul.rn.f32x2 %0, %1, %2;" : "=l"(d) : "l"(a), "l"(b)); return d;
}
__device__ __forceinline__ u64 f2fma(u64 a, u64 b, u64 c) {
    u64 d; asm("fma.rn.f32x2 %0, %1, %2, %3;" : "=l"(d) : "l"(a), "l"(b), "l"(c)); return d;
}
__device__ __forceinline__ u64 f2rsqrt(u64 v) {
    float lo, hi; f2up(v, lo, hi); return f2pk(rsqrtf(lo), rsqrtf(hi));
}
__device__ __forceinline__ u64 f2tanh(u64 v) {
    float lo, hi; f2up(v, lo, hi); return f2pk(tanh_approx(lo), tanh_approx(hi));
}
__device__ __forceinline__ u64 ldg64(const float* p) {
    return __ldg(reinterpret_cast<const u64*>(p));
}

// ---------- scalar erf pieces ----------
__device__ __forceinline__ float erf_tanh(float x) {
    return tanh_approx(x * fmaf(EK3, x * x, EK1));
}
__device__ __forceinline__ float erf_small(float x, float u) {
    float p = fmaf(u, fmaf(u, fmaf(u, -2.3809524e-2f, 0.1f), -0.33333334f), 1.0f);
    return 1.1283791671f * x * p;
}

__device__ __forceinline__ float block_reduce_sum(float v) {
    __shared__ float s[32];
    int lane = threadIdx.x & 31;
    int w    = threadIdx.x >> 5;
    #pragma unroll
    for (int o = 16; o; o >>= 1) v += __shfl_xor_sync(0xffffffffu, v, o);
    if (lane == 0) s[w] = v;
    __syncthreads();
    v = (threadIdx.x < (TPB >> 5)) ? s[threadIdx.x] : 0.0f;
    if (w == 0) {
        #pragma unroll
        for (int o = 16; o; o >>= 1) v += __shfl_xor_sync(0xffffffffu, v, o);
    }
    return v;  // valid in thread 0
}

// scalar pair term
template <bool T0ZERO>
__device__ __forceinline__ float pair_term(float2 zi, float2 vi,
                                           float2 zj, float2 vj,
                                           float b, float t0, float tn) {
    float dzx = zi.x - zj.x, dzy = zi.y - zj.y;
    float dvx = vi.x - vj.x, dvy = vi.y - vj.y;
    float a2 = fmaf(dzx, dzx, dzy * dzy);
    float b2 = fmaf(dvx, dvx, dvy * dvy);
    float ab = fmaf(dzx, dvx, dzy * dvy);
    float rb = rsqrtf(b2);
    float bn = b2 * rb;
    float q  = ab * rb;
    float u  = q * q;
    float earg  = (b - a2) + u;
    float pref  = ex2_approx(earg * L2E) * (SQRTPI_2 * rb);
    float e1 = erf_tanh(fmaf(bn, tn, q));
    float e0 = T0ZERO ? erf_small(q, u) : erf_tanh(fmaf(bn, t0, q));
    return pref * (e1 - e0);
}

// ---------- prep: staging + counter reset ----------
__global__ void prep(const float2* __restrict__ z0,
                     const float2* __restrict__ v0, int n) {
    int m = blockIdx.x * blockDim.x + threadIdx.x;
    if (m == 0) g_ctr = 0;
    if (m < NPAD) {
        int src = (n > 0) ? (m % n) : 0;
        float2 z = z0[src], v = v0[src];
        g_nzx[m] = -z.x; g_nzy[m] = -z.y;
        g_nvx[m] = -v.x; g_nvy[m] = -v.y;
        g_zv[m]  = make_float4(z.x, z.y, v.x, v.y);
    }
}

__global__ void __launch_bounds__(TPB, 4)
cvm_fused(const int2*   __restrict__ idx,
          const float*  __restrict__ t,
          const float2* __restrict__ z0,
          const float2* __restrict__ v0,
          const float*  __restrict__ t0p,
          const float*  __restrict__ tnp,
          const float*  __restrict__ betap,
          float*        __restrict__ out,
          int n, int n_events, int cch) {
    const float b  = __ldg(betap);
    const float t0 = __ldg(t0p);
    const float tn = __ldg(tnp);
    const float eb886 = SQRTPI_2 * ex2_approx(b * L2E);
    float acc = 0.0f;

    const int wid = (int)threadIdx.x >> 5;
    const int lid = (int)threadIdx.x & 31;
    const int ew  = (int)blockIdx.x & 7;   // event-warp id (rotates over SMSPs)

    if (wid == ew) {
        // ================= EVENT WARP =================
        const int nlanes = (int)gridDim.x * 32;
        const int base   = (int)blockIdx.x * 32 + lid;
        const bool use_tbl = (n <= NPAD);
        for (int e = base; e < n_events; e += nlanes) {
            int2  ij = __ldg(&idx[e]);
            float te = __ldg(&t[e]);
            float dx, dy;
            if (use_tbl) {
                float4 pi = __ldg(&g_zv[ij.x]);
                float4 pj = __ldg(&g_zv[ij.y]);
                dx = fmaf(pi.z - pj.z, te, pi.x - pj.x);
                dy = fmaf(pi.w - pj.w, te, pi.y - pj.y);
            } else {
                float2 zi = __ldg(&z0[ij.x]), zj = __ldg(&z0[ij.y]);
                float2 vi = __ldg(&v0[ij.x]), vj = __ldg(&v0[ij.y]);
                dx = fmaf(vi.x - vj.x, te, zi.x - zj.x);
                dy = fmaf(vi.y - vj.y, te, zi.y - zj.y);
            }
            acc = fmaf(dx, dx, acc);
            acc = fmaf(dy, dy, acc);
        }
    } else {
        // ================= PAIR WARPS =================
        const int widx = (wid < ew) ? wid : wid - 1;           // 0..6
        const int tgl  = (int)blockIdx.x * (PWPB * 32) + widx * 32 + lid;
        const int i    = tgl % n;
        const int c    = tgl / n;
        const int kfull = (n - 1) >> 1;
        const bool haveHalf = ((n & 1) == 0);

        if (c < cch && n >= 3) {
            const int cbase = kfull / cch, crem = kfull % cch;
            const int kbeg  = 1 + c * cbase + (c < crem ? c : crem);
            const int klen  = cbase + (c < crem ? 1 : 0);

            const float2 zi = __ldg(&z0[i]);
            const float2 vi = __ldg(&v0[i]);

            const bool t0z = (t0 == 0.0f) && (n + kfull + 2 <= NPAD);

            if (t0z) {
                int j0 = i + kbeg;          // mirrored arrays absorb wrap
                int j1 = j0 + klen;

                if (j0 & 1) {               // LDG.64 alignment peel
                    int jm = (j0 >= n) ? j0 - n : j0;
                    acc += pair_term<true>(zi, vi, __ldg(&z0[jm]), __ldg(&v0[jm]),
                                           b, 0.0f, tn);
                    j0++;
                }
                int jp_end = j0 + ((j1 - j0) & ~1);

                const u64 zxi = f2pk(zi.x, zi.x), zyi = f2pk(zi.y, zi.y);
                const u64 vxi = f2pk(vi.x, vi.x), vyi = f2pk(vi.y, vi.y);
                const u64 NEG1 = f2pk(-1.0f, -1.0f);
                const u64 ONE2 = f2pk(1.0f, 1.0f);
                const u64 TN2  = f2pk(tn, tn);
                const u64 K1   = f2pk(EK1, EK1);
                const u64 K3   = f2pk(EK3, EK3);
                const u64 T0n  = f2pk(-1.1283791671f, -1.1283791671f);
                const u64 T1n  = f2pk(0.3761263890f, 0.3761263890f);
                const u64 T2n  = f2pk(-0.1128379167f, -0.1128379167f);
                const u64 T3n  = f2pk(0.0268661706f, 0.0268661706f);
                const u64 C120 = f2pk(8.3333333e-3f, 8.3333333e-3f);
                const u64 C24  = f2pk(4.1666667e-2f, 4.1666667e-2f);
                const u64 C6_  = f2pk(0.16666667f, 0.16666667f);
                const u64 C2_  = f2pk(0.5f, 0.5f);
                const u64 EB   = f2pk(eb886, eb886);

                u64 acc2 = 0;
                #pragma unroll 2
                for (int J = j0; J < jp_end; J += 2) {
                    u64 nzjx = ldg64(g_nzx + J);
                    u64 nzjy = ldg64(g_nzy + J);
                    u64 nvjx = ldg64(g_nvx + J);
                    u64 nvjy = ldg64(g_nvy + J);

                    u64 dzx = f2add(zxi, nzjx);
                    u64 dzy = f2add(zyi, nzjy);
                    u64 dvx = f2add(vxi, nvjx);
                    u64 dvy = f2add(vyi, nvjy);

                    u64 a2 = f2fma(dzx, dzx, f2mul(dzy, dzy));
                    u64 b2 = f2fma(dvx, dvx, f2mul(dvy, dvy));
                    u64 ab = f2fma(dzx, dvx, f2mul(dzy, dvy));

                    u64 rb = f2rsqrt(b2);
                    u64 bn = f2mul(b2, rb);
                    u64 q  = f2mul(ab, rb);
                    u64 u  = f2mul(q, q);
                    u64 w  = f2fma(a2, NEG1, u);   // q^2 - a2 in [-0.5, 0]

                    u64 p  = f2fma(w, C120, C24);  // exp(w) Taylor deg-5
                    p      = f2fma(w, p, C6_);
                    p      = f2fma(w, p, C2_);
                    p      = f2fma(w, p, ONE2);
                    u64 P  = f2fma(w, p, ONE2);
                    u64 pref = f2mul(f2mul(rb, EB), P);

                    u64 e0n = f2mul(q, f2fma(u, f2fma(u, f2fma(u, T3n, T2n), T1n), T0n));

                    u64 x1 = f2fma(bn, TN2, q);
                    u64 h  = f2mul(x1, f2fma(K3, f2mul(x1, x1), K1));
                    u64 e1 = f2tanh(h);

                    acc2 = f2fma(pref, f2add(e1, e0n), acc2);
                }
                float lo, hi; f2up(acc2, lo, hi);
                acc += lo + hi;

                if (j1 > jp_end) {          // odd-tail peel
                    int jm = (jp_end >= n) ? jp_end - n : jp_end;
                    acc += pair_term<true>(zi, vi, __ldg(&z0[jm]), __ldg(&v0[jm]),
                                           b, 0.0f, tn);
                }
                if (haveHalf && c == cch - 1 && i < (n >> 1)) {
                    int jm = i + (n >> 1);
                    acc += pair_term<true>(zi, vi, __ldg(&z0[jm]), __ldg(&v0[jm]),
                                           b, 0.0f, tn);
                }
            } else {
                for (int k = kbeg; k < kbeg + klen; k++) {
                    int jm = i + k; if (jm >= n) jm -= n;
                    acc += pair_term<false>(zi, vi, __ldg(&z0[jm]), __ldg(&v0[jm]),
                                            b, t0, tn);
                }
                if (haveHalf && c == cch - 1 && i < (n >> 1)) {
                    int jm = i + (n >> 1);
                    acc += pair_term<false>(zi, vi, __ldg(&z0[jm]), __ldg(&v0[jm]),
                                            b, t0, tn);
                }
            }
        }
    }

    float bs = block_reduce_sum(acc);
    __shared__ unsigned int s_rank;
    if (threadIdx.x == 0) {
        g_part[blockIdx.x] = bs;
        __threadfence();
        s_rank = atomicAdd(&g_ctr, 1u);
    }
    __syncthreads();

    if (s_rank == gridDim.x - 1) {
        __threadfence();
        double d = 0.0;
        for (int k = threadIdx.x; k < (int)gridDim.x; k += TPB)
            d += (double)g_part[k];
        __shared__ double sd[32];
        int lane = threadIdx.x & 31, w = threadIdx.x >> 5;
        #pragma unroll
        for (int o = 16; o; o >>= 1) d += __shfl_xor_sync(0xffffffffu, d, o);
        if (lane == 0) sd[w] = d;
        __syncthreads();
        d = (threadIdx.x < (TPB >> 5)) ? sd[threadIdx.x] : 0.0;
        if (w == 0) {
            #pragma unroll
            for (int o = 16; o; o >>= 1) d += __shfl_xor_sync(0xffffffffu, d, o);
        }
        if (threadIdx.x == 0)
            out[0] = (float)((double)n_events * (double)b - d);
    }
}

extern "C" void kernel_launch(void* const* d_in, const int* in_sizes, int n_in,
                              void* d_out, int out_size) {
    const int2*   idx  = (const int2*)d_in[0];    // (N_EVENTS, 2) int32
    const float*  t    = (const float*)d_in[1];   // (N_EVENTS,)
    const float*  t0   = (const float*)d_in[2];   // scalar
    const float*  tn   = (const float*)d_in[3];   // scalar
    const float2* z0   = (const float2*)d_in[4];  // (N_POINTS, 2)
    const float2* v0   = (const float2*)d_in[5];  // (N_POINTS, 2)
    const float*  beta = (const float*)d_in[6];   // (1,1)

    const int n_events = in_sizes[1];
    const int n_points = in_sizes[4] / 2;

    prep<<<(NPAD + 255) / 256, 256>>>(z0, v0, n_points);

    int grid = 4 * 148;                       // one wave, 4 blocks/SM
    int pair_lanes = grid * PWPB * 32;        // 132,608
    int cch = pair_lanes / (n_points > 0 ? n_points : 1);
    if (cch < 1) cch = 1;

    cvm_fused<<<grid, TPB>>>(idx, t, z0, v0, t0, tn, beta,
                             (float*)d_out, n_points, n_events, cch);
}

// round 13
// speedup vs baseline: 1.0779x; 1.0702x over previous
#include <cuda_runtime.h>

#define TPB  256
#define MAXB 1024
#define NPAD 8192
#define PWPB 7     // pair warps per block (1 warp does events)
#define BPSM 5     // blocks per SM

typedef unsigned long long u64;

__device__ float        g_part[MAXB];
__device__ unsigned int g_ctr;
// negated SoA, mirrored past n (pairs); raw packed float4 (event gathers)
__device__ __align__(16) float  g_nzx[NPAD];
__device__ __align__(16) float  g_nzy[NPAD];
__device__ __align__(16) float  g_nvx[NPAD];
__device__ __align__(16) float  g_nvy[NPAD];
__device__ __align__(16) float4 g_zv [NPAD];

__device__ __forceinline__ float ex2_approx(float x) {
    float r; asm("ex2.approx.f32 %0, %1;" : "=f"(r) : "f"(x)); return r;
}
__device__ __forceinline__ float tanh_approx(float x) {
    float r; asm("tanh.approx.f32 %0, %1;" : "=f"(r) : "f"(x)); return r;
}
#define L2E 1.4426950408889634f
#define EK1 1.1283792f
#define EK3 0.100906f
#define SQRTPI_2 0.88622692545275801f

// ---------- packed f32x2 helpers ----------
__device__ __forceinline__ u64 f2pk(float lo, float hi) {
    u64 r; asm("mov.b64 %0, {%1, %2};" : "=l"(r) : "f"(lo), "f"(hi)); return r;
}
__device__ __forceinline__ void f2up(u64 v, float& lo, float& hi) {
    asm("mov.b64 {%0, %1}, %2;" : "=f"(lo), "=f"(hi) : "l"(v));
}
__device__ __forceinline__ u64 f2add(u64 a, u64 b) {
    u64 d; asm("add.rn.f32x2 %0, %1, %2;" : "=l"(d) : "l"(a), "l"(b)); return d;
}
__device__ __forceinline__ u64 f2mul(u64 a, u64 b) {
    u64 d; asm("mul.rn.f32x2 %0, %1, %2;" : "=l"(d) : "l"(a), "l"(b)); return d;
}
__device__ __forceinline__ u64 f2fma(u64 a, u64 b, u64 c) {
    u64 d; asm("fma.rn.f32x2 %0, %1, %2, %3;" : "=l"(d) : "l"(a), "l"(b), "l"(c)); return d;
}
__device__ __forceinline__ u64 f2rsqrt(u64 v) {
    float lo, hi; f2up(v, lo, hi); return f2pk(rsqrtf(lo), rsqrtf(hi));
}
__device__ __forceinline__ u64 f2tanh(u64 v) {
    float lo, hi; f2up(v, lo, hi); return f2pk(tanh_approx(lo), tanh_approx(hi));
}
__device__ __forceinline__ u64 ldg64(const float* p) {
    return __ldg(reinterpret_cast<const u64*>(p));
}

// ---------- scalar erf pieces ----------
__device__ __forceinline__ float erf_tanh(float x) {
    return tanh_approx(x * fmaf(EK3, x * x, EK1));
}
__device__ __forceinline__ float erf_small(float x, float u) {
    float p = fmaf(u, fmaf(u, fmaf(u, -2.3809524e-2f, 0.1f), -0.33333334f), 1.0f);
    return 1.1283791671f * x * p;
}

__device__ __forceinline__ float block_reduce_sum(float v) {
    __shared__ float s[32];
    int lane = threadIdx.x & 31;
    int w    = threadIdx.x >> 5;
    #pragma unroll
    for (int o = 16; o; o >>= 1) v += __shfl_xor_sync(0xffffffffu, v, o);
    if (lane == 0) s[w] = v;
    __syncthreads();
    v = (threadIdx.x < (TPB >> 5)) ? s[threadIdx.x] : 0.0f;
    if (w == 0) {
        #pragma unroll
        for (int o = 16; o; o >>= 1) v += __shfl_xor_sync(0xffffffffu, v, o);
    }
    return v;  // valid in thread 0
}

// scalar pair term
template <bool T0ZERO>
__device__ __forceinline__ float pair_term(float2 zi, float2 vi,
                                           float2 zj, float2 vj,
                                           float b, float t0, float tn) {
    float dzx = zi.x - zj.x, dzy = zi.y - zj.y;
    float dvx = vi.x - vj.x, dvy = vi.y - vj.y;
    float a2 = fmaf(dzx, dzx, dzy * dzy);
    float b2 = fmaf(dvx, dvx, dvy * dvy);
    float ab = fmaf(dzx, dvx, dzy * dvy);
    float rb = rsqrtf(b2);
    float bn = b2 * rb;
    float q  = ab * rb;
    float u  = q * q;
    float earg  = (b - a2) + u;
    float pref  = ex2_approx(earg * L2E) * (SQRTPI_2 * rb);
    float e1 = erf_tanh(fmaf(bn, tn, q));
    float e0 = T0ZERO ? erf_small(q, u) : erf_tanh(fmaf(bn, t0, q));
    return pref * (e1 - e0);
}

// ---------- prep: staging + counter reset ----------
__global__ void prep(const float2* __restrict__ z0,
                     const float2* __restrict__ v0, int n) {
    int m = blockIdx.x * blockDim.x + threadIdx.x;
    if (m == 0) g_ctr = 0;
    if (m < NPAD) {
        int src = (n > 0) ? (m % n) : 0;
        float2 z = z0[src], v = v0[src];
        g_nzx[m] = -z.x; g_nzy[m] = -z.y;
        g_nvx[m] = -v.x; g_nvy[m] = -v.y;
        g_zv[m]  = make_float4(z.x, z.y, v.x, v.y);
    }
}

__global__ void __launch_bounds__(TPB, BPSM)
cvm_fused(const int2*   __restrict__ idx,
          const float*  __restrict__ t,
          const float2* __restrict__ z0,
          const float2* __restrict__ v0,
          const float*  __restrict__ t0p,
          const float*  __restrict__ tnp,
          const float*  __restrict__ betap,
          float*        __restrict__ out,
          int n, int n_events, int cch) {
    const float b  = __ldg(betap);
    const float t0 = __ldg(t0p);
    const float tn = __ldg(tnp);
    const float eb886 = SQRTPI_2 * ex2_approx(b * L2E);
    float acc = 0.0f;

    const int wid = (int)threadIdx.x >> 5;
    const int lid = (int)threadIdx.x & 31;
    const int ew  = (int)blockIdx.x & 7;   // event-warp id (rotates over SMSPs)

    if (wid == ew) {
        // ================= EVENT WARP =================
        const int nlanes = (int)gridDim.x * 32;
        const int base   = (int)blockIdx.x * 32 + lid;
        const bool use_tbl = (n <= NPAD);
        if (use_tbl) {
            for (int e = base; e < n_events; e += nlanes) {
                int2  ij = __ldg(&idx[e]);
                float te = __ldg(&t[e]);
                float4 pi = __ldg(&g_zv[ij.x]);
                float4 pj = __ldg(&g_zv[ij.y]);
                float dx = fmaf(pi.z - pj.z, te, pi.x - pj.x);
                float dy = fmaf(pi.w - pj.w, te, pi.y - pj.y);
                acc = fmaf(dx, dx, acc);
                acc = fmaf(dy, dy, acc);
            }
        } else {
            for (int e = base; e < n_events; e += nlanes) {
                int2  ij = __ldg(&idx[e]);
                float te = __ldg(&t[e]);
                float2 zi = __ldg(&z0[ij.x]), zj = __ldg(&z0[ij.y]);
                float2 vi = __ldg(&v0[ij.x]), vj = __ldg(&v0[ij.y]);
                float dx = fmaf(vi.x - vj.x, te, zi.x - zj.x);
                float dy = fmaf(vi.y - vj.y, te, zi.y - zj.y);
                acc = fmaf(dx, dx, acc);
                acc = fmaf(dy, dy, acc);
            }
        }
    } else {
        // ================= PAIR WARPS =================
        const int widx = (wid < ew) ? wid : wid - 1;           // 0..6
        const int tgl  = (int)blockIdx.x * (PWPB * 32) + widx * 32 + lid;
        const int i    = tgl % n;
        const int c    = tgl / n;
        const int kfull = (n - 1) >> 1;
        const bool haveHalf = ((n & 1) == 0);

        if (c < cch && n >= 3) {
            const int cbase = kfull / cch, crem = kfull % cch;
            const int kbeg  = 1 + c * cbase + (c < crem ? c : crem);
            const int klen  = cbase + (c < crem ? 1 : 0);

            const float2 zi = __ldg(&z0[i]);
            const float2 vi = __ldg(&v0[i]);

            const bool t0z = (t0 == 0.0f) && (n + kfull + 2 <= NPAD);

            if (t0z) {
                int j0 = i + kbeg;          // mirrored arrays absorb wrap
                int j1 = j0 + klen;

                if (j0 & 1) {               // LDG.64 alignment peel
                    int jm = (j0 >= n) ? j0 - n : j0;
                    acc += pair_term<true>(zi, vi, __ldg(&z0[jm]), __ldg(&v0[jm]),
                                           b, 0.0f, tn);
                    j0++;
                }
                int jp_end = j0 + ((j1 - j0) & ~1);

                const u64 zxi = f2pk(zi.x, zi.x), zyi = f2pk(zi.y, zi.y);
                const u64 vxi = f2pk(vi.x, vi.x), vyi = f2pk(vi.y, vi.y);
                const u64 NEG1 = f2pk(-1.0f, -1.0f);
                const u64 ONE2 = f2pk(1.0f, 1.0f);
                const u64 TN2  = f2pk(tn, tn);
                const u64 K1   = f2pk(EK1, EK1);
                const u64 K3   = f2pk(EK3, EK3);
                const u64 T0n  = f2pk(-1.1283791671f, -1.1283791671f);
                const u64 T1n  = f2pk(0.3761263890f, 0.3761263890f);
                const u64 T2n  = f2pk(-0.1128379167f, -0.1128379167f);
                const u64 T3n  = f2pk(0.0268661706f, 0.0268661706f);
                // exp(w) Taylor deg-4 (|w| <= 0.5)
                const u64 C24  = f2pk(4.1666667e-2f, 4.1666667e-2f);
                const u64 C6_  = f2pk(0.16666667f, 0.16666667f);
                const u64 C2_  = f2pk(0.5f, 0.5f);
                const u64 EB   = f2pk(eb886, eb886);

                u64 acc2 = 0;
                #pragma unroll 2
                for (int J = j0; J < jp_end; J += 2) {
                    u64 nzjx = ldg64(g_nzx + J);
                    u64 nzjy = ldg64(g_nzy + J);
                    u64 nvjx = ldg64(g_nvx + J);
                    u64 nvjy = ldg64(g_nvy + J);

                    u64 dzx = f2add(zxi, nzjx);
                    u64 dzy = f2add(zyi, nzjy);
                    u64 dvx = f2add(vxi, nvjx);
                    u64 dvy = f2add(vyi, nvjy);

                    u64 a2 = f2fma(dzx, dzx, f2mul(dzy, dzy));
                    u64 b2 = f2fma(dvx, dvx, f2mul(dvy, dvy));
                    u64 ab = f2fma(dzx, dvx, f2mul(dzy, dvy));

                    u64 rb = f2rsqrt(b2);
                    u64 bn = f2mul(b2, rb);
                    u64 q  = f2mul(ab, rb);
                    u64 u  = f2mul(q, q);
                    u64 w  = f2fma(a2, NEG1, u);   // q^2 - a2 in [-0.5, 0]

                    u64 p  = f2fma(w, C24, C6_);   // exp(w) Taylor deg-4
                    p      = f2fma(w, p, C2_);
                    p      = f2fma(w, p, ONE2);
                    u64 P  = f2fma(w, p, ONE2);
                    u64 pref = f2mul(f2mul(rb, EB), P);

                    u64 e0n = f2mul(q, f2fma(u, f2fma(u, f2fma(u, T3n, T2n), T1n), T0n));

                    u64 x1 = f2fma(bn, TN2, q);
                    u64 h  = f2mul(x1, f2fma(K3, f2mul(x1, x1), K1));
                    u64 e1 = f2tanh(h);

                    acc2 = f2fma(pref, f2add(e1, e0n), acc2);
                }
                float lo, hi; f2up(acc2, lo, hi);
                acc += lo + hi;

                if (j1 > jp_end) {          // odd-tail peel
                    int jm = (jp_end >= n) ? jp_end - n : jp_end;
                    acc += pair_term<true>(zi, vi, __ldg(&z0[jm]), __ldg(&v0[jm]),
                                           b, 0.0f, tn);
                }
                if (haveHalf && c == cch - 1 && i < (n >> 1)) {
                    int jm = i + (n >> 1);
                    acc += pair_term<true>(zi, vi, __ldg(&z0[jm]), __ldg(&v0[jm]),
                                           b, 0.0f, tn);
                }
            } else {
                for (int k = kbeg; k < kbeg + klen; k++) {
                    int jm = i + k; if (jm >= n) jm -= n;
                    acc += pair_term<false>(zi, vi, __ldg(&z0[jm]), __ldg(&v0[jm]),
                                            b, t0, tn);
                }
                if (haveHalf && c == cch - 1 && i < (n >> 1)) {
                    int jm = i + (n >> 1);
                    acc += pair_term<false>(zi, vi, __ldg(&z0[jm]), __ldg(&v0[jm]),
                                            b, t0, tn);
                }
            }
        }
    }

    float bs = block_reduce_sum(acc);
    __shared__ unsigned int s_rank;
    if (threadIdx.x == 0) {
        g_part[blockIdx.x] = bs;
        __threadfence();
        s_rank = atomicAdd(&g_ctr, 1u);
    }
    __syncthreads();

    if (s_rank == gridDim.x - 1) {
        __threadfence();
        double d = 0.0;
        for (int k = threadIdx.x; k < (int)gridDim.x; k += TPB)
            d += (double)g_part[k];
        __shared__ double sd[32];
        int lane = threadIdx.x & 31, w = threadIdx.x >> 5;
        #pragma unroll
        for (int o = 16; o; o >>= 1) d += __shfl_xor_sync(0xffffffffu, d, o);
        if (lane == 0) sd[w] = d;
        __syncthreads();
        d = (threadIdx.x < (TPB >> 5)) ? sd[threadIdx.x] : 0.0;
        if (w == 0) {
            #pragma unroll
            for (int o = 16; o; o >>= 1) d += __shfl_xor_sync(0xffffffffu, d, o);
        }
        if (threadIdx.x == 0)
            out[0] = (float)((double)n_events * (double)b - d);
    }
}

extern "C" void kernel_launch(void* const* d_in, const int* in_sizes, int n_in,
                              void* d_out, int out_size) {
    const int2*   idx  = (const int2*)d_in[0];    // (N_EVENTS, 2) int32
    const float*  t    = (const float*)d_in[1];   // (N_EVENTS,)
    const float*  t0   = (const float*)d_in[2];   // scalar
    const float*  tn   = (const float*)d_in[3];   // scalar
    const float2* z0   = (const float2*)d_in[4];  // (N_POINTS, 2)
    const float2* v0   = (const float2*)d_in[5];  // (N_POINTS, 2)
    const float*  beta = (const float*)d_in[6];   // (1,1)

    const int n_events = in_sizes[1];
    const int n_points = in_sizes[4] / 2;

    prep<<<(NPAD + 255) / 256, 256>>>(z0, v0, n_points);

    int grid = BPSM * 148;                    // one wave, 5 blocks/SM
    int pair_lanes = grid * PWPB * 32;        // 165,760
    int cch = pair_lanes / (n_points > 0 ? n_points : 1);
    if (cch < 1) cch = 1;

    cvm_fused<<<grid, TPB>>>(idx, t, z0, v0, t0, tn, beta,
                             (float*)d_out, n_points, n_events, cch);
}